// round 10
// baseline (speedup 1.0000x reference)
#include <cuda_runtime.h>
#include <math.h>

#define NN 50000
#define EMAXE 900000
#define SPLIT 25088   // node split for msg0f/gemm1 pipelining (multiple of 128)

// ---------------- scratch (device globals) -----------------------------------
__device__ float  g_h0[(size_t)NN * 256];
__device__ float  g_out0[(size_t)NN * 256];
__device__ float  g_h1[(size_t)NN * 128];
__device__ float  g_ssrc0[NN * 2];
__device__ float  g_sdst0[NN * 2];
__device__ float  g_ssrc1[NN];
__device__ float  g_sdst1[NN];
__device__ int    g_cnt[NN];
__device__ int    g_off[NN + 1];
__device__ int    g_cursor[NN];
__device__ int    g_csrc[EMAXE];

__device__ __forceinline__ float lrelu(float v) { return v > 0.f ? v : 0.2f * v; }

// ---------------- CSR build ---------------------------------------------------
__global__ void filli(int* __restrict__ p, int n, int v) {
    int i = blockIdx.x * blockDim.x + threadIdx.x;
    if (i < n) p[i] = v;
}

__global__ void histK(const int* __restrict__ dst, int E0, int* __restrict__ cnt) {
    int e = blockIdx.x * blockDim.x + threadIdx.x;
    if (e < E0) atomicAdd(&cnt[dst[e]], 1);
}

__global__ __launch_bounds__(1024) void scanK(const int* __restrict__ cnt,
                                              int* __restrict__ off,
                                              int* __restrict__ cursor) {
    __shared__ int wsum[32];
    __shared__ int s_carry;
    int tid = threadIdx.x;
    int lane = tid & 31, warp = tid >> 5;
    if (tid == 0) s_carry = 0;
    __syncthreads();
    for (int base = 0; base < NN; base += 1024) {
        int i = base + tid;
        int v = (i < NN) ? cnt[i] : 0;
        int s = v;
#pragma unroll
        for (int o = 1; o < 32; o <<= 1) {
            int t = __shfl_up_sync(0xffffffffu, s, o);
            if (lane >= o) s += t;
        }
        if (lane == 31) wsum[warp] = s;
        __syncthreads();
        if (warp == 0) {
            int ws = wsum[lane];
#pragma unroll
            for (int o = 1; o < 32; o <<= 1) {
                int t = __shfl_up_sync(0xffffffffu, ws, o);
                if (lane >= o) ws += t;
            }
            wsum[lane] = ws;
        }
        __syncthreads();
        int excl = s - v + (warp ? wsum[warp - 1] : 0) + s_carry;
        if (i < NN) { off[i] = excl; cursor[i] = excl; }
        __syncthreads();
        if (tid == 1023) s_carry = excl + v;
        __syncthreads();
    }
    if (tid == 0) off[NN] = s_carry;
}

__global__ void scatterK(const int* __restrict__ src, const int* __restrict__ dst,
                         int E0, int Etot, int* __restrict__ cursor,
                         int* __restrict__ csrc) {
    int e = blockIdx.x * blockDim.x + threadIdx.x;
    if (e >= Etot) return;
    int s, d;
    if (e < E0) { s = src[e]; d = dst[e]; } else { s = d = e - E0; }
    int p = atomicAdd(&cursor[d], 1);
    csrc[p] = s;
}

// ---------------- GEMM + fused attention scores -------------------------------
__global__ __launch_bounds__(256, 2) void gemmS(const float* __restrict__ A,
                                                const float* __restrict__ B,
                                                float* __restrict__ C,
                                                const float* __restrict__ a_src,
                                                const float* __restrict__ a_dst,
                                                float* __restrict__ ssrc,
                                                float* __restrict__ sdst,
                                                int M, int N, int K, int H,
                                                int rowBase) {
    __shared__ float As[2][8][132];
    __shared__ float Bs[2][8][132];
    int bm = rowBase + blockIdx.y * 128, bn = blockIdx.x * 128;
    int head = blockIdx.x;
    int tid = threadIdx.x;
    int ty = tid >> 4, tx = tid & 15;
    float acc[8][8];
#pragma unroll
    for (int i = 0; i < 8; i++)
#pragma unroll
        for (int j = 0; j < 8; j++) acc[i][j] = 0.f;

    int ra = tid >> 1;
    int ca = (tid & 1) * 4;
    int rb = tid >> 5;
    int cb = (tid & 31) * 4;
    const float* Ap = A + (size_t)(bm + ra) * K + ca;
    bool aval = (bm + ra) < M;

    float4 av = make_float4(0.f, 0.f, 0.f, 0.f);
    if (aval) av = *(const float4*)Ap;
    float4 bv = *(const float4*)(B + (size_t)rb * N + bn + cb);
    As[0][ca + 0][ra] = av.x; As[0][ca + 1][ra] = av.y;
    As[0][ca + 2][ra] = av.z; As[0][ca + 3][ra] = av.w;
    *(float4*)&Bs[0][rb][cb] = bv;
    __syncthreads();

    int buf = 0;
    for (int k0 = 0; k0 < K; k0 += 8) {
        bool more = (k0 + 8) < K;
        float4 av2, bv2;
        if (more) {
            av2 = make_float4(0.f, 0.f, 0.f, 0.f);
            if (aval) av2 = *(const float4*)(Ap + k0 + 8);
            bv2 = *(const float4*)(B + (size_t)(k0 + 8 + rb) * N + bn + cb);
        }
#pragma unroll
        for (int k = 0; k < 8; k++) {
            float a[8], b[8];
            *(float4*)(a)     = *(const float4*)&As[buf][k][ty * 4];
            *(float4*)(a + 4) = *(const float4*)&As[buf][k][64 + ty * 4];
            *(float4*)(b)     = *(const float4*)&Bs[buf][k][tx * 4];
            *(float4*)(b + 4) = *(const float4*)&Bs[buf][k][64 + tx * 4];
#pragma unroll
            for (int i = 0; i < 8; i++)
#pragma unroll
                for (int j = 0; j < 8; j++) acc[i][j] += a[i] * b[j];
        }
        if (more) {
            int nb = buf ^ 1;
            As[nb][ca + 0][ra] = av2.x; As[nb][ca + 1][ra] = av2.y;
            As[nb][ca + 2][ra] = av2.z; As[nb][ca + 3][ra] = av2.w;
            *(float4*)&Bs[nb][rb][cb] = bv2;
            __syncthreads();
            buf = nb;
        }
    }

#pragma unroll
    for (int i = 0; i < 8; i++) {
        int gr = bm + ((i < 4) ? (ty * 4 + i) : (64 + ty * 4 + i - 4));
        if (gr < M) {
            float4 v0 = make_float4(acc[i][0], acc[i][1], acc[i][2], acc[i][3]);
            float4 v1 = make_float4(acc[i][4], acc[i][5], acc[i][6], acc[i][7]);
            *(float4*)(C + (size_t)gr * N + bn + tx * 4) = v0;
            *(float4*)(C + (size_t)gr * N + bn + 64 + tx * 4) = v1;
        }
    }

    float as[8], ad[8];
#pragma unroll
    for (int j = 0; j < 4; j++) {
        as[j]     = a_src[head * 128 + tx * 4 + j];
        as[4 + j] = a_src[head * 128 + 64 + tx * 4 + j];
        ad[j]     = a_dst[head * 128 + tx * 4 + j];
        ad[4 + j] = a_dst[head * 128 + 64 + tx * 4 + j];
    }
#pragma unroll
    for (int i = 0; i < 8; i++) {
        float ps = 0.f, pd = 0.f;
#pragma unroll
        for (int j = 0; j < 8; j++) {
            ps += acc[i][j] * as[j];
            pd += acc[i][j] * ad[j];
        }
#pragma unroll
        for (int o = 8; o >= 1; o >>= 1) {
            ps += __shfl_xor_sync(0xffffffffu, ps, o);
            pd += __shfl_xor_sync(0xffffffffu, pd, o);
        }
        int gr = bm + ((i < 4) ? (ty * 4 + i) : (64 + ty * 4 + i - 4));
        if (tx == 0 && gr < M) {
            ssrc[gr * H + head] = ps;
            sdst[gr * H + head] = pd;
        }
    }
}

// ---------------- layer0 fused softmax+aggregate+bias+ELU ----------------------
// 2 nodes/block; per node 2 warps (one per head). Edge weights computed once per
// warp per edge (lane-parallel over 32-edge chunks, broadcast via shfl).
__global__ __launch_bounds__(128) void msg0f(const int* __restrict__ off,
                                             const int* __restrict__ csrc,
                                             const float* __restrict__ ssrc,
                                             const float* __restrict__ sdst,
                                             const float* __restrict__ h,
                                             const float* __restrict__ b0,
                                             float* __restrict__ out,
                                             int nodeBase, int nodeEnd) {
    int node = nodeBase + blockIdx.x * 2 + (threadIdx.x >> 6);
    if (node >= nodeEnd) return;
    int lane = threadIdx.x & 31;
    int head = (threadIdx.x >> 5) & 1;
    int begin = off[node], end = off[node + 1];
    float sd = sdst[node * 2 + head];
    const float* hb = h + head * 128 + lane * 4;
    float4 acc0 = make_float4(0.f, 0.f, 0.f, 0.f);
    float4 acc1 = make_float4(0.f, 0.f, 0.f, 0.f);
    float4 acc2 = make_float4(0.f, 0.f, 0.f, 0.f);
    float4 acc3 = make_float4(0.f, 0.f, 0.f, 0.f);
    float wsum = 0.f;
    for (int c = begin; c < end; c += 32) {
        int n = end - c; if (n > 32) n = 32;
        int sL = 0; float aL = 0.f;
        if (lane < n) {
            sL = csrc[c + lane];
            aL = __expf(lrelu(ssrc[sL * 2 + head] + sd));
        }
        wsum += aL;
        int k = 0;
        for (; k + 4 <= n; k += 4) {
            float a0 = __shfl_sync(0xffffffffu, aL, k);
            int   s0 = __shfl_sync(0xffffffffu, sL, k);
            float a1 = __shfl_sync(0xffffffffu, aL, k + 1);
            int   s1 = __shfl_sync(0xffffffffu, sL, k + 1);
            float a2 = __shfl_sync(0xffffffffu, aL, k + 2);
            int   s2 = __shfl_sync(0xffffffffu, sL, k + 2);
            float a3 = __shfl_sync(0xffffffffu, aL, k + 3);
            int   s3 = __shfl_sync(0xffffffffu, sL, k + 3);
            float4 v0 = *(const float4*)(hb + (size_t)s0 * 256);
            float4 v1 = *(const float4*)(hb + (size_t)s1 * 256);
            float4 v2 = *(const float4*)(hb + (size_t)s2 * 256);
            float4 v3 = *(const float4*)(hb + (size_t)s3 * 256);
            acc0.x += a0 * v0.x; acc0.y += a0 * v0.y; acc0.z += a0 * v0.z; acc0.w += a0 * v0.w;
            acc1.x += a1 * v1.x; acc1.y += a1 * v1.y; acc1.z += a1 * v1.z; acc1.w += a1 * v1.w;
            acc2.x += a2 * v2.x; acc2.y += a2 * v2.y; acc2.z += a2 * v2.z; acc2.w += a2 * v2.w;
            acc3.x += a3 * v3.x; acc3.y += a3 * v3.y; acc3.z += a3 * v3.z; acc3.w += a3 * v3.w;
        }
        for (; k < n; k++) {
            float a0 = __shfl_sync(0xffffffffu, aL, k);
            int   s0 = __shfl_sync(0xffffffffu, sL, k);
            float4 v0 = *(const float4*)(hb + (size_t)s0 * 256);
            acc0.x += a0 * v0.x; acc0.y += a0 * v0.y; acc0.z += a0 * v0.z; acc0.w += a0 * v0.w;
        }
    }
#pragma unroll
    for (int o = 16; o > 0; o >>= 1) wsum += __shfl_xor_sync(0xffffffffu, wsum, o);
    float r = 1.f / wsum;
    float4 bb = *(const float4*)(b0 + head * 128 + lane * 4);
    float vx = (acc0.x + acc1.x + acc2.x + acc3.x) * r + bb.x;
    float vy = (acc0.y + acc1.y + acc2.y + acc3.y) * r + bb.y;
    float vz = (acc0.z + acc1.z + acc2.z + acc3.z) * r + bb.z;
    float vw = (acc0.w + acc1.w + acc2.w + acc3.w) * r + bb.w;
    float4 o;
    o.x = vx > 0.f ? vx : (expf(vx) - 1.f);
    o.y = vy > 0.f ? vy : (expf(vy) - 1.f);
    o.z = vz > 0.f ? vz : (expf(vz) - 1.f);
    o.w = vw > 0.f ? vw : (expf(vw) - 1.f);
    *(float4*)(out + (size_t)node * 256 + head * 128 + lane * 4) = o;
}

// ---------------- layer1 fused softmax+aggregate+residual+bias -----------------
__global__ __launch_bounds__(128) void msg1f(const int* __restrict__ off,
                                             const int* __restrict__ csrc,
                                             const float* __restrict__ ssrc,
                                             const float* __restrict__ sdst,
                                             const float* __restrict__ h,
                                             const float* __restrict__ x,
                                             const float* __restrict__ b1,
                                             float* __restrict__ out) {
    int node = blockIdx.x * 4 + (threadIdx.x >> 5);
    if (node >= NN) return;
    int lane = threadIdx.x & 31;
    int begin = off[node], end = off[node + 1];
    float sd = sdst[node];
    const float* hb = h + lane * 4;
    float4 acc0 = make_float4(0.f, 0.f, 0.f, 0.f);
    float4 acc1 = make_float4(0.f, 0.f, 0.f, 0.f);
    float4 acc2 = make_float4(0.f, 0.f, 0.f, 0.f);
    float4 acc3 = make_float4(0.f, 0.f, 0.f, 0.f);
    float wsum = 0.f;
    for (int c = begin; c < end; c += 32) {
        int n = end - c; if (n > 32) n = 32;
        int sL = 0; float aL = 0.f;
        if (lane < n) {
            sL = csrc[c + lane];
            aL = __expf(lrelu(ssrc[sL] + sd));
        }
        wsum += aL;
        int k = 0;
        for (; k + 4 <= n; k += 4) {
            float a0 = __shfl_sync(0xffffffffu, aL, k);
            int   s0 = __shfl_sync(0xffffffffu, sL, k);
            float a1 = __shfl_sync(0xffffffffu, aL, k + 1);
            int   s1 = __shfl_sync(0xffffffffu, sL, k + 1);
            float a2 = __shfl_sync(0xffffffffu, aL, k + 2);
            int   s2 = __shfl_sync(0xffffffffu, sL, k + 2);
            float a3 = __shfl_sync(0xffffffffu, aL, k + 3);
            int   s3 = __shfl_sync(0xffffffffu, sL, k + 3);
            float4 v0 = *(const float4*)(hb + (size_t)s0 * 128);
            float4 v1 = *(const float4*)(hb + (size_t)s1 * 128);
            float4 v2 = *(const float4*)(hb + (size_t)s2 * 128);
            float4 v3 = *(const float4*)(hb + (size_t)s3 * 128);
            acc0.x += a0 * v0.x; acc0.y += a0 * v0.y; acc0.z += a0 * v0.z; acc0.w += a0 * v0.w;
            acc1.x += a1 * v1.x; acc1.y += a1 * v1.y; acc1.z += a1 * v1.z; acc1.w += a1 * v1.w;
            acc2.x += a2 * v2.x; acc2.y += a2 * v2.y; acc2.z += a2 * v2.z; acc2.w += a2 * v2.w;
            acc3.x += a3 * v3.x; acc3.y += a3 * v3.y; acc3.z += a3 * v3.z; acc3.w += a3 * v3.w;
        }
        for (; k < n; k++) {
            float a0 = __shfl_sync(0xffffffffu, aL, k);
            int   s0 = __shfl_sync(0xffffffffu, sL, k);
            float4 v0 = *(const float4*)(hb + (size_t)s0 * 128);
            acc0.x += a0 * v0.x; acc0.y += a0 * v0.y; acc0.z += a0 * v0.z; acc0.w += a0 * v0.w;
        }
    }
#pragma unroll
    for (int o = 16; o > 0; o >>= 1) wsum += __shfl_xor_sync(0xffffffffu, wsum, o);
    float r = 1.f / wsum;
    float4 xb = *(const float4*)(x + (size_t)node * 128 + lane * 4);
    float4 bb = *(const float4*)(b1 + lane * 4);
    float4 o;
    o.x = (acc0.x + acc1.x + acc2.x + acc3.x) * r + xb.x + bb.x;
    o.y = (acc0.y + acc1.y + acc2.y + acc3.y) * r + xb.y + bb.y;
    o.z = (acc0.z + acc1.z + acc2.z + acc3.z) * r + xb.z + bb.z;
    o.w = (acc0.w + acc1.w + acc2.w + acc3.w) * r + xb.w + bb.w;
    *(float4*)(out + (size_t)node * 128 + lane * 4) = o;
}

// ---------------- launch -------------------------------------------------------
extern "C" void kernel_launch(void* const* d_in, const int* in_sizes, int n_in,
                              void* d_out, int out_size) {
    const float* x      = (const float*)d_in[0];
    const float* W0     = (const float*)d_in[1];
    const float* a_src0 = (const float*)d_in[2];
    const float* a_dst0 = (const float*)d_in[3];
    const float* b0     = (const float*)d_in[4];
    const float* W1     = (const float*)d_in[5];
    const float* a_src1 = (const float*)d_in[6];
    const float* a_dst1 = (const float*)d_in[7];
    const float* b1     = (const float*)d_in[8];
    const int*   ei     = (const int*)d_in[9];
    int E0 = in_sizes[9] / 2;
    int Etot = E0 + NN;
    const int* src = ei;
    const int* dst = ei + E0;
    float* out = (float*)d_out;

    float *h0, *out0, *h1, *ssrc0, *sdst0, *ssrc1, *sdst1;
    int *cnt, *off, *cursor, *csrc;
    cudaGetSymbolAddress((void**)&h0, g_h0);
    cudaGetSymbolAddress((void**)&out0, g_out0);
    cudaGetSymbolAddress((void**)&h1, g_h1);
    cudaGetSymbolAddress((void**)&ssrc0, g_ssrc0);
    cudaGetSymbolAddress((void**)&sdst0, g_sdst0);
    cudaGetSymbolAddress((void**)&ssrc1, g_ssrc1);
    cudaGetSymbolAddress((void**)&sdst1, g_sdst1);
    cudaGetSymbolAddress((void**)&cnt, g_cnt);
    cudaGetSymbolAddress((void**)&off, g_off);
    cudaGetSymbolAddress((void**)&cursor, g_cursor);
    cudaGetSymbolAddress((void**)&csrc, g_csrc);

    cudaStream_t sB;
    cudaStreamCreateWithFlags(&sB, cudaStreamNonBlocking);
    cudaEvent_t evFork, evB, evM0a, evG1a;
    cudaEventCreateWithFlags(&evFork, cudaEventDisableTiming);
    cudaEventCreateWithFlags(&evB, cudaEventDisableTiming);
    cudaEventCreateWithFlags(&evM0a, cudaEventDisableTiming);
    cudaEventCreateWithFlags(&evG1a, cudaEventDisableTiming);

    cudaEventRecord(evFork, 0);
    cudaStreamWaitEvent(sB, evFork, 0);

    // ---- CSR build on side stream (overlaps layer0 GEMM) ----
    filli<<<(NN + 255) / 256, 256, 0, sB>>>(cnt, NN, 1);
    histK<<<(E0 + 255) / 256, 256, 0, sB>>>(dst, E0, cnt);
    scanK<<<1, 1024, 0, sB>>>(cnt, off, cursor);
    scatterK<<<(Etot + 255) / 256, 256, 0, sB>>>(src, dst, E0, Etot, cursor, csrc);
    cudaEventRecord(evB, sB);

    // ---- layer 0 GEMM (full) ----
    gemmS<<<dim3(2, (NN + 127) / 128), 256>>>(x, W0, h0, a_src0, a_dst0,
                                              ssrc0, sdst0, NN, 256, 128, 2, 0);
    cudaStreamWaitEvent(0, evB, 0);

    // ---- msg0f chunk A (nodes [0, SPLIT)) ----
    msg0f<<<SPLIT / 2, 128>>>(off, csrc, ssrc0, sdst0, h0, b0, out0, 0, SPLIT);
    cudaEventRecord(evM0a, 0);

    // ---- gemm1 chunk A on side stream (rows [0, SPLIT)) — overlaps msg0f B ----
    cudaStreamWaitEvent(sB, evM0a, 0);
    gemmS<<<dim3(1, SPLIT / 128), 256, 0, sB>>>(out0, W1, h1, a_src1, a_dst1,
                                                ssrc1, sdst1, NN, 128, 256, 1, 0);
    cudaEventRecord(evG1a, sB);

    // ---- msg0f chunk B (nodes [SPLIT, NN)) on main ----
    msg0f<<<(NN - SPLIT + 1) / 2, 128>>>(off, csrc, ssrc0, sdst0, h0, b0, out0,
                                         SPLIT, NN);

    // ---- gemm1 chunk B on main (rows [SPLIT, NN)) ----
    gemmS<<<dim3(1, (NN - SPLIT + 127) / 128), 256>>>(out0, W1, h1, a_src1, a_dst1,
                                                      ssrc1, sdst1, NN, 128, 256, 1,
                                                      SPLIT);
    cudaStreamWaitEvent(0, evG1a, 0);

    // ---- msg1f (full) ----
    msg1f<<<(NN + 3) / 4, 128>>>(off, csrc, ssrc1, sdst1, h1, x, b1, out);

    cudaEventDestroy(evFork);
    cudaEventDestroy(evB);
    cudaEventDestroy(evM0a);
    cudaEventDestroy(evG1a);
    cudaStreamDestroy(sB);
}

// round 11
// speedup vs baseline: 1.0827x; 1.0827x over previous
#include <cuda_runtime.h>
#include <cuda_fp16.h>
#include <math.h>

#define NN 50000
#define EMAXE 900000
#define SPLIT 25088   // node split for msg0f/gemm1 pipelining (multiple of 128)

// ---------------- scratch (device globals) -----------------------------------
__device__ __half g_h0[(size_t)NN * 256];   // layer0 features, fp16 (gathered)
__device__ float  g_out0[(size_t)NN * 256]; // layer0 output, fp32 (GEMM1 input)
__device__ __half g_h1[(size_t)NN * 128];   // layer1 features, fp16 (gathered)
__device__ float  g_ssrc0[NN * 2];
__device__ float  g_sdst0[NN * 2];
__device__ float  g_ssrc1[NN];
__device__ float  g_sdst1[NN];
__device__ int    g_cnt[NN];
__device__ int    g_off[NN + 1];
__device__ int    g_cursor[NN];
__device__ int    g_csrc[EMAXE];

__device__ __forceinline__ float lrelu(float v) { return v > 0.f ? v : 0.2f * v; }

// ---------------- CSR build ---------------------------------------------------
__global__ void filli(int* __restrict__ p, int n, int v) {
    int i = blockIdx.x * blockDim.x + threadIdx.x;
    if (i < n) p[i] = v;
}

__global__ void histK(const int* __restrict__ dst, int E0, int* __restrict__ cnt) {
    int e = blockIdx.x * blockDim.x + threadIdx.x;
    if (e < E0) atomicAdd(&cnt[dst[e]], 1);
}

__global__ __launch_bounds__(1024) void scanK(const int* __restrict__ cnt,
                                              int* __restrict__ off,
                                              int* __restrict__ cursor) {
    __shared__ int wsum[32];
    __shared__ int s_carry;
    int tid = threadIdx.x;
    int lane = tid & 31, warp = tid >> 5;
    if (tid == 0) s_carry = 0;
    __syncthreads();
    for (int base = 0; base < NN; base += 1024) {
        int i = base + tid;
        int v = (i < NN) ? cnt[i] : 0;
        int s = v;
#pragma unroll
        for (int o = 1; o < 32; o <<= 1) {
            int t = __shfl_up_sync(0xffffffffu, s, o);
            if (lane >= o) s += t;
        }
        if (lane == 31) wsum[warp] = s;
        __syncthreads();
        if (warp == 0) {
            int ws = wsum[lane];
#pragma unroll
            for (int o = 1; o < 32; o <<= 1) {
                int t = __shfl_up_sync(0xffffffffu, ws, o);
                if (lane >= o) ws += t;
            }
            wsum[lane] = ws;
        }
        __syncthreads();
        int excl = s - v + (warp ? wsum[warp - 1] : 0) + s_carry;
        if (i < NN) { off[i] = excl; cursor[i] = excl; }
        __syncthreads();
        if (tid == 1023) s_carry = excl + v;
        __syncthreads();
    }
    if (tid == 0) off[NN] = s_carry;
}

__global__ void scatterK(const int* __restrict__ src, const int* __restrict__ dst,
                         int E0, int Etot, int* __restrict__ cursor,
                         int* __restrict__ csrc) {
    int e = blockIdx.x * blockDim.x + threadIdx.x;
    if (e >= Etot) return;
    int s, d;
    if (e < E0) { s = src[e]; d = dst[e]; } else { s = d = e - E0; }
    int p = atomicAdd(&cursor[d], 1);
    csrc[p] = s;
}

// ---------------- GEMM (fp32 in, fp16 out) + fused attention scores -----------
__global__ __launch_bounds__(256, 2) void gemmS(const float* __restrict__ A,
                                                const float* __restrict__ B,
                                                __half* __restrict__ C,
                                                const float* __restrict__ a_src,
                                                const float* __restrict__ a_dst,
                                                float* __restrict__ ssrc,
                                                float* __restrict__ sdst,
                                                int M, int N, int K, int H,
                                                int rowBase) {
    __shared__ float As[2][8][132];
    __shared__ float Bs[2][8][132];
    int bm = rowBase + blockIdx.y * 128, bn = blockIdx.x * 128;
    int head = blockIdx.x;
    int tid = threadIdx.x;
    int ty = tid >> 4, tx = tid & 15;
    float acc[8][8];
#pragma unroll
    for (int i = 0; i < 8; i++)
#pragma unroll
        for (int j = 0; j < 8; j++) acc[i][j] = 0.f;

    int ra = tid >> 1;
    int ca = (tid & 1) * 4;
    int rb = tid >> 5;
    int cb = (tid & 31) * 4;
    const float* Ap = A + (size_t)(bm + ra) * K + ca;
    bool aval = (bm + ra) < M;

    float4 av = make_float4(0.f, 0.f, 0.f, 0.f);
    if (aval) av = *(const float4*)Ap;
    float4 bv = *(const float4*)(B + (size_t)rb * N + bn + cb);
    As[0][ca + 0][ra] = av.x; As[0][ca + 1][ra] = av.y;
    As[0][ca + 2][ra] = av.z; As[0][ca + 3][ra] = av.w;
    *(float4*)&Bs[0][rb][cb] = bv;
    __syncthreads();

    int buf = 0;
    for (int k0 = 0; k0 < K; k0 += 8) {
        bool more = (k0 + 8) < K;
        float4 av2, bv2;
        if (more) {
            av2 = make_float4(0.f, 0.f, 0.f, 0.f);
            if (aval) av2 = *(const float4*)(Ap + k0 + 8);
            bv2 = *(const float4*)(B + (size_t)(k0 + 8 + rb) * N + bn + cb);
        }
#pragma unroll
        for (int k = 0; k < 8; k++) {
            float a[8], b[8];
            *(float4*)(a)     = *(const float4*)&As[buf][k][ty * 4];
            *(float4*)(a + 4) = *(const float4*)&As[buf][k][64 + ty * 4];
            *(float4*)(b)     = *(const float4*)&Bs[buf][k][tx * 4];
            *(float4*)(b + 4) = *(const float4*)&Bs[buf][k][64 + tx * 4];
#pragma unroll
            for (int i = 0; i < 8; i++)
#pragma unroll
                for (int j = 0; j < 8; j++) acc[i][j] += a[i] * b[j];
        }
        if (more) {
            int nb = buf ^ 1;
            As[nb][ca + 0][ra] = av2.x; As[nb][ca + 1][ra] = av2.y;
            As[nb][ca + 2][ra] = av2.z; As[nb][ca + 3][ra] = av2.w;
            *(float4*)&Bs[nb][rb][cb] = bv2;
            __syncthreads();
            buf = nb;
        }
    }

    // store C (fp16)
#pragma unroll
    for (int i = 0; i < 8; i++) {
        int gr = bm + ((i < 4) ? (ty * 4 + i) : (64 + ty * 4 + i - 4));
        if (gr < M) {
            __half2 p0 = __floats2half2_rn(acc[i][0], acc[i][1]);
            __half2 p1 = __floats2half2_rn(acc[i][2], acc[i][3]);
            __half2 p2 = __floats2half2_rn(acc[i][4], acc[i][5]);
            __half2 p3 = __floats2half2_rn(acc[i][6], acc[i][7]);
            __half2* cp0 = (__half2*)(C + (size_t)gr * N + bn + tx * 4);
            cp0[0] = p0; cp0[1] = p1;
            __half2* cp1 = (__half2*)(C + (size_t)gr * N + bn + 64 + tx * 4);
            cp1[0] = p2; cp1[1] = p3;
        }
    }

    // fused attention scores for this head (from fp32 accumulators)
    float as[8], ad[8];
#pragma unroll
    for (int j = 0; j < 4; j++) {
        as[j]     = a_src[head * 128 + tx * 4 + j];
        as[4 + j] = a_src[head * 128 + 64 + tx * 4 + j];
        ad[j]     = a_dst[head * 128 + tx * 4 + j];
        ad[4 + j] = a_dst[head * 128 + 64 + tx * 4 + j];
    }
#pragma unroll
    for (int i = 0; i < 8; i++) {
        float ps = 0.f, pd = 0.f;
#pragma unroll
        for (int j = 0; j < 8; j++) {
            ps += acc[i][j] * as[j];
            pd += acc[i][j] * ad[j];
        }
#pragma unroll
        for (int o = 8; o >= 1; o >>= 1) {
            ps += __shfl_xor_sync(0xffffffffu, ps, o);
            pd += __shfl_xor_sync(0xffffffffu, pd, o);
        }
        int gr = bm + ((i < 4) ? (ty * 4 + i) : (64 + ty * 4 + i - 4));
        if (tx == 0 && gr < M) {
            ssrc[gr * H + head] = ps;
            sdst[gr * H + head] = pd;
        }
    }
}

// ---------------- layer0 fused softmax+aggregate+bias+ELU ----------------------
// 1 warp per node; lane handles 8 halves (16B gather). Lanes 0-15 = head0,
// 16-31 = head1. Per-lane exp is redundant but 1 warp-instr/edge; wsum needs
// no reduction (every lane of a head sees every edge).
__global__ __launch_bounds__(128) void msg0f(const int* __restrict__ off,
                                             const int* __restrict__ csrc,
                                             const float* __restrict__ ssrc,
                                             const float* __restrict__ sdst,
                                             const __half* __restrict__ h,
                                             const float* __restrict__ b0,
                                             float* __restrict__ out,
                                             int nodeBase, int nodeEnd) {
    int node = nodeBase + blockIdx.x * 4 + (threadIdx.x >> 5);
    if (node >= nodeEnd) return;
    int lane = threadIdx.x & 31;
    int head = lane >> 4;
    int begin = off[node], end = off[node + 1];
    float sd = sdst[node * 2 + head];
    const __half* hb = h + lane * 8;
    float2 acc[4][4];
#pragma unroll
    for (int q = 0; q < 4; q++)
#pragma unroll
        for (int k = 0; k < 4; k++) acc[q][k] = make_float2(0.f, 0.f);
    float wsum = 0.f;
    int j = begin;
    for (; j + 4 <= end; j += 4) {
        int s0 = csrc[j], s1 = csrc[j + 1], s2 = csrc[j + 2], s3 = csrc[j + 3];
        float a0 = __expf(lrelu(ssrc[s0 * 2 + head] + sd));
        float a1 = __expf(lrelu(ssrc[s1 * 2 + head] + sd));
        float a2 = __expf(lrelu(ssrc[s2 * 2 + head] + sd));
        float a3 = __expf(lrelu(ssrc[s3 * 2 + head] + sd));
        wsum += (a0 + a1) + (a2 + a3);
        uint4 u0 = *(const uint4*)(hb + (size_t)s0 * 256);
        uint4 u1 = *(const uint4*)(hb + (size_t)s1 * 256);
        uint4 u2 = *(const uint4*)(hb + (size_t)s2 * 256);
        uint4 u3 = *(const uint4*)(hb + (size_t)s3 * 256);
#define ACC0(q, u, a)                                                     \
        {                                                                 \
            float2 f0 = __half22float2(*(const __half2*)&u.x);            \
            float2 f1 = __half22float2(*(const __half2*)&u.y);            \
            float2 f2 = __half22float2(*(const __half2*)&u.z);            \
            float2 f3 = __half22float2(*(const __half2*)&u.w);            \
            acc[q][0].x += a * f0.x; acc[q][0].y += a * f0.y;             \
            acc[q][1].x += a * f1.x; acc[q][1].y += a * f1.y;             \
            acc[q][2].x += a * f2.x; acc[q][2].y += a * f2.y;             \
            acc[q][3].x += a * f3.x; acc[q][3].y += a * f3.y;             \
        }
        ACC0(0, u0, a0) ACC0(1, u1, a1) ACC0(2, u2, a2) ACC0(3, u3, a3)
    }
    for (; j < end; j++) {
        int s0 = csrc[j];
        float a0 = __expf(lrelu(ssrc[s0 * 2 + head] + sd));
        wsum += a0;
        uint4 u0 = *(const uint4*)(hb + (size_t)s0 * 256);
        ACC0(0, u0, a0)
    }
#undef ACC0
    float r = 1.f / wsum;
    float4 bbA = *(const float4*)(b0 + lane * 8);
    float4 bbB = *(const float4*)(b0 + lane * 8 + 4);
    float v[8];
    v[0] = (acc[0][0].x + acc[1][0].x + acc[2][0].x + acc[3][0].x) * r + bbA.x;
    v[1] = (acc[0][0].y + acc[1][0].y + acc[2][0].y + acc[3][0].y) * r + bbA.y;
    v[2] = (acc[0][1].x + acc[1][1].x + acc[2][1].x + acc[3][1].x) * r + bbA.z;
    v[3] = (acc[0][1].y + acc[1][1].y + acc[2][1].y + acc[3][1].y) * r + bbA.w;
    v[4] = (acc[0][2].x + acc[1][2].x + acc[2][2].x + acc[3][2].x) * r + bbB.x;
    v[5] = (acc[0][2].y + acc[1][2].y + acc[2][2].y + acc[3][2].y) * r + bbB.y;
    v[6] = (acc[0][3].x + acc[1][3].x + acc[2][3].x + acc[3][3].x) * r + bbB.z;
    v[7] = (acc[0][3].y + acc[1][3].y + acc[2][3].y + acc[3][3].y) * r + bbB.w;
#pragma unroll
    for (int k = 0; k < 8; k++) v[k] = v[k] > 0.f ? v[k] : (expf(v[k]) - 1.f);
    float* op = out + (size_t)node * 256 + lane * 8;
    *(float4*)(op)     = make_float4(v[0], v[1], v[2], v[3]);
    *(float4*)(op + 4) = make_float4(v[4], v[5], v[6], v[7]);
}

// ---------------- layer1 fused softmax+aggregate+residual+bias -----------------
__global__ __launch_bounds__(128) void msg1f(const int* __restrict__ off,
                                             const int* __restrict__ csrc,
                                             const float* __restrict__ ssrc,
                                             const float* __restrict__ sdst,
                                             const __half* __restrict__ h,
                                             const float* __restrict__ x,
                                             const float* __restrict__ b1,
                                             float* __restrict__ out) {
    int node = blockIdx.x * 4 + (threadIdx.x >> 5);
    if (node >= NN) return;
    int lane = threadIdx.x & 31;
    int begin = off[node], end = off[node + 1];
    float sd = sdst[node];
    const __half* hb = h + lane * 4;
    float2 acc[4][2];
#pragma unroll
    for (int q = 0; q < 4; q++) {
        acc[q][0] = make_float2(0.f, 0.f);
        acc[q][1] = make_float2(0.f, 0.f);
    }
    float wsum = 0.f;
    int j = begin;
    for (; j + 4 <= end; j += 4) {
        int s0 = csrc[j], s1 = csrc[j + 1], s2 = csrc[j + 2], s3 = csrc[j + 3];
        float a0 = __expf(lrelu(ssrc[s0] + sd));
        float a1 = __expf(lrelu(ssrc[s1] + sd));
        float a2 = __expf(lrelu(ssrc[s2] + sd));
        float a3 = __expf(lrelu(ssrc[s3] + sd));
        wsum += (a0 + a1) + (a2 + a3);
        uint2 u0 = *(const uint2*)(hb + (size_t)s0 * 128);
        uint2 u1 = *(const uint2*)(hb + (size_t)s1 * 128);
        uint2 u2 = *(const uint2*)(hb + (size_t)s2 * 128);
        uint2 u3 = *(const uint2*)(hb + (size_t)s3 * 128);
#define ACC1(q, u, a)                                                     \
        {                                                                 \
            float2 f0 = __half22float2(*(const __half2*)&u.x);            \
            float2 f1 = __half22float2(*(const __half2*)&u.y);            \
            acc[q][0].x += a * f0.x; acc[q][0].y += a * f0.y;             \
            acc[q][1].x += a * f1.x; acc[q][1].y += a * f1.y;             \
        }
        ACC1(0, u0, a0) ACC1(1, u1, a1) ACC1(2, u2, a2) ACC1(3, u3, a3)
    }
    for (; j < end; j++) {
        int s0 = csrc[j];
        float a0 = __expf(lrelu(ssrc[s0] + sd));
        wsum += a0;
        uint2 u0 = *(const uint2*)(hb + (size_t)s0 * 128);
        ACC1(0, u0, a0)
    }
#undef ACC1
    float r = 1.f / wsum;
    float4 xb = *(const float4*)(x + (size_t)node * 128 + lane * 4);
    float4 bb = *(const float4*)(b1 + lane * 4);
    float4 o;
    o.x = (acc[0][0].x + acc[1][0].x + acc[2][0].x + acc[3][0].x) * r + xb.x + bb.x;
    o.y = (acc[0][0].y + acc[1][0].y + acc[2][0].y + acc[3][0].y) * r + xb.y + bb.y;
    o.z = (acc[0][1].x + acc[1][1].x + acc[2][1].x + acc[3][1].x) * r + xb.z + bb.z;
    o.w = (acc[0][1].y + acc[1][1].y + acc[2][1].y + acc[3][1].y) * r + xb.w + bb.w;
    *(float4*)(out + (size_t)node * 128 + lane * 4) = o;
}

// ---------------- launch -------------------------------------------------------
extern "C" void kernel_launch(void* const* d_in, const int* in_sizes, int n_in,
                              void* d_out, int out_size) {
    const float* x      = (const float*)d_in[0];
    const float* W0     = (const float*)d_in[1];
    const float* a_src0 = (const float*)d_in[2];
    const float* a_dst0 = (const float*)d_in[3];
    const float* b0     = (const float*)d_in[4];
    const float* W1     = (const float*)d_in[5];
    const float* a_src1 = (const float*)d_in[6];
    const float* a_dst1 = (const float*)d_in[7];
    const float* b1     = (const float*)d_in[8];
    const int*   ei     = (const int*)d_in[9];
    int E0 = in_sizes[9] / 2;
    int Etot = E0 + NN;
    const int* src = ei;
    const int* dst = ei + E0;
    float* out = (float*)d_out;

    __half *h0, *h1;
    float *out0, *ssrc0, *sdst0, *ssrc1, *sdst1;
    int *cnt, *off, *cursor, *csrc;
    cudaGetSymbolAddress((void**)&h0, g_h0);
    cudaGetSymbolAddress((void**)&out0, g_out0);
    cudaGetSymbolAddress((void**)&h1, g_h1);
    cudaGetSymbolAddress((void**)&ssrc0, g_ssrc0);
    cudaGetSymbolAddress((void**)&sdst0, g_sdst0);
    cudaGetSymbolAddress((void**)&ssrc1, g_ssrc1);
    cudaGetSymbolAddress((void**)&sdst1, g_sdst1);
    cudaGetSymbolAddress((void**)&cnt, g_cnt);
    cudaGetSymbolAddress((void**)&off, g_off);
    cudaGetSymbolAddress((void**)&cursor, g_cursor);
    cudaGetSymbolAddress((void**)&csrc, g_csrc);

    cudaStream_t sB;
    cudaStreamCreateWithFlags(&sB, cudaStreamNonBlocking);
    cudaEvent_t evFork, evB, evM0a, evG1a;
    cudaEventCreateWithFlags(&evFork, cudaEventDisableTiming);
    cudaEventCreateWithFlags(&evB, cudaEventDisableTiming);
    cudaEventCreateWithFlags(&evM0a, cudaEventDisableTiming);
    cudaEventCreateWithFlags(&evG1a, cudaEventDisableTiming);

    cudaEventRecord(evFork, 0);
    cudaStreamWaitEvent(sB, evFork, 0);

    // ---- CSR build on side stream (overlaps layer0 GEMM) ----
    filli<<<(NN + 255) / 256, 256, 0, sB>>>(cnt, NN, 1);
    histK<<<(E0 + 255) / 256, 256, 0, sB>>>(dst, E0, cnt);
    scanK<<<1, 1024, 0, sB>>>(cnt, off, cursor);
    scatterK<<<(Etot + 255) / 256, 256, 0, sB>>>(src, dst, E0, Etot, cursor, csrc);
    cudaEventRecord(evB, sB);

    // ---- layer 0 GEMM (full) ----
    gemmS<<<dim3(2, (NN + 127) / 128), 256>>>(x, W0, h0, a_src0, a_dst0,
                                              ssrc0, sdst0, NN, 256, 128, 2, 0);
    cudaStreamWaitEvent(0, evB, 0);

    // ---- msg0f chunk A (nodes [0, SPLIT)) ----
    msg0f<<<SPLIT / 4, 128>>>(off, csrc, ssrc0, sdst0, h0, b0, out0, 0, SPLIT);
    cudaEventRecord(evM0a, 0);

    // ---- gemm1 chunk A on side stream (rows [0, SPLIT)) — overlaps msg0f B ----
    cudaStreamWaitEvent(sB, evM0a, 0);
    gemmS<<<dim3(1, SPLIT / 128), 256, 0, sB>>>(out0, W1, h1, a_src1, a_dst1,
                                                ssrc1, sdst1, NN, 128, 256, 1, 0);
    cudaEventRecord(evG1a, sB);

    // ---- msg0f chunk B (nodes [SPLIT, NN)) on main ----
    msg0f<<<(NN - SPLIT + 3) / 4, 128>>>(off, csrc, ssrc0, sdst0, h0, b0, out0,
                                         SPLIT, NN);

    // ---- gemm1 chunk B on main (rows [SPLIT, NN)) ----
    gemmS<<<dim3(1, (NN - SPLIT + 127) / 128), 256>>>(out0, W1, h1, a_src1, a_dst1,
                                                      ssrc1, sdst1, NN, 128, 256, 1,
                                                      SPLIT);
    cudaStreamWaitEvent(0, evG1a, 0);

    // ---- msg1f (full) ----
    msg1f<<<(NN + 3) / 4, 128>>>(off, csrc, ssrc1, sdst1, h1, x, b1, out);

    cudaEventDestroy(evFork);
    cudaEventDestroy(evB);
    cudaEventDestroy(evM0a);
    cudaEventDestroy(evG1a);
    cudaStreamDestroy(sB);
}

// round 12
// speedup vs baseline: 1.7703x; 1.6352x over previous
#include <cuda_runtime.h>
#include <cuda_fp16.h>
#include <mma.h>
#include <math.h>

using namespace nvcuda;

#define NN 50000
#define EMAXE 900000
#define SPLIT 25088   // node split for msg0f/gemm1 pipelining (multiple of 128)

// ---------------- scratch (device globals) -----------------------------------
__device__ __half g_xh[(size_t)NN * 128];    // x in fp16 (GEMM0 A)
__device__ __half g_W0h[128 * 256];
__device__ __half g_W1h[256 * 128];
__device__ __half g_h0[(size_t)NN * 256];    // layer0 features, fp16
__device__ __half g_out0h[(size_t)NN * 256]; // layer0 output, fp16 (GEMM1 A)
__device__ __half g_h1[(size_t)NN * 128];    // layer1 features, fp16
__device__ float  g_ssrc0[NN * 2];
__device__ float  g_sdst0[NN * 2];
__device__ float  g_ssrc1[NN];
__device__ float  g_sdst1[NN];
__device__ int    g_cnt[NN];
__device__ int    g_off[NN + 1];
__device__ int    g_cursor[NN];
__device__ int    g_csrc[EMAXE];

__device__ __forceinline__ float lrelu(float v) { return v > 0.f ? v : 0.2f * v; }

// ---------------- fp32 -> fp16 convert ----------------------------------------
__global__ void f2h(const float* __restrict__ in, __half* __restrict__ out, int n4) {
    int i = blockIdx.x * blockDim.x + threadIdx.x;
    if (i < n4) {
        float4 v = ((const float4*)in)[i];
        __half2 p0 = __floats2half2_rn(v.x, v.y);
        __half2 p1 = __floats2half2_rn(v.z, v.w);
        ((uint2*)out)[i] = make_uint2(*(unsigned*)&p0, *(unsigned*)&p1);
    }
}

// ---------------- CSR build ---------------------------------------------------
__global__ void filli(int* __restrict__ p, int n, int v) {
    int i = blockIdx.x * blockDim.x + threadIdx.x;
    if (i < n) p[i] = v;
}

__global__ void histK(const int* __restrict__ dst, int E0, int* __restrict__ cnt) {
    int e = blockIdx.x * blockDim.x + threadIdx.x;
    if (e < E0) atomicAdd(&cnt[dst[e]], 1);
}

__global__ __launch_bounds__(1024) void scanK(const int* __restrict__ cnt,
                                              int* __restrict__ off,
                                              int* __restrict__ cursor) {
    __shared__ int wsum[32];
    __shared__ int s_carry;
    int tid = threadIdx.x;
    int lane = tid & 31, warp = tid >> 5;
    if (tid == 0) s_carry = 0;
    __syncthreads();
    for (int base = 0; base < NN; base += 1024) {
        int i = base + tid;
        int v = (i < NN) ? cnt[i] : 0;
        int s = v;
#pragma unroll
        for (int o = 1; o < 32; o <<= 1) {
            int t = __shfl_up_sync(0xffffffffu, s, o);
            if (lane >= o) s += t;
        }
        if (lane == 31) wsum[warp] = s;
        __syncthreads();
        if (warp == 0) {
            int ws = wsum[lane];
#pragma unroll
            for (int o = 1; o < 32; o <<= 1) {
                int t = __shfl_up_sync(0xffffffffu, ws, o);
                if (lane >= o) ws += t;
            }
            wsum[lane] = ws;
        }
        __syncthreads();
        int excl = s - v + (warp ? wsum[warp - 1] : 0) + s_carry;
        if (i < NN) { off[i] = excl; cursor[i] = excl; }
        __syncthreads();
        if (tid == 1023) s_carry = excl + v;
        __syncthreads();
    }
    if (tid == 0) off[NN] = s_carry;
}

__global__ void scatterK(const int* __restrict__ src, const int* __restrict__ dst,
                         int E0, int Etot, int* __restrict__ cursor,
                         int* __restrict__ csrc) {
    int e = blockIdx.x * blockDim.x + threadIdx.x;
    if (e >= Etot) return;
    int s, d;
    if (e < E0) { s = src[e]; d = dst[e]; } else { s = d = e - E0; }
    int p = atomicAdd(&cursor[d], 1);
    csrc[p] = s;
}

// ---------------- tensor-core GEMM + fused scores ------------------------------
// C[M,N] = A[M,K]@B[K,N], A/B fp16, acc fp32, C out fp16. 128x128 tile, 8 warps,
// warp = 64x32 (4x2 wmma frags). Epilogue stages fp32 C tile in smem for the
// a_src/a_dst score reduction and the fp16 C store.
#define SMA 24                       // A smem row stride (halfs)
#define SMB 136                      // B smem row stride (halfs)
#define SMC 132                      // C smem row stride (floats)
#define GEMM_SMEM (128 * SMC * 4)    // 67584 bytes (C tile; aliases A/B)

__global__ __launch_bounds__(256) void gemmW(const __half* __restrict__ A,
                                             const __half* __restrict__ B,
                                             __half* __restrict__ C,
                                             const float* __restrict__ a_src,
                                             const float* __restrict__ a_dst,
                                             float* __restrict__ ssrc,
                                             float* __restrict__ sdst,
                                             int M, int N, int K, int H,
                                             int rowBase) {
    extern __shared__ char smem[];
    __half* sA = (__half*)smem;                    // [128][SMA]
    __half* sB = (__half*)(smem + 128 * SMA * 2);  // [16][SMB]
    float*  sC = (float*)smem;                     // [128][SMC] (post-loop)

    int bm = rowBase + blockIdx.y * 128, bn = blockIdx.x * 128;
    int head = blockIdx.x;
    int tid = threadIdx.x;
    int wid = tid >> 5;
    int wm = wid >> 2, wn = wid & 3;   // warp tile origin: (wm*64, wn*32)

    wmma::fragment<wmma::accumulator, 16, 16, 16, float> fc[4][2];
#pragma unroll
    for (int i = 0; i < 4; i++)
#pragma unroll
        for (int j = 0; j < 2; j++) wmma::fill_fragment(fc[i][j], 0.f);

    int raA = tid >> 1, caA = (tid & 1) * 8;     // A: 128 rows x 16 cols
    int raB = tid >> 4, caB = (tid & 15) * 8;    // B: 16 rows x 128 cols

    for (int k0 = 0; k0 < K; k0 += 16) {
        __syncthreads();
        {
            uint4 v = make_uint4(0, 0, 0, 0);
            if (bm + raA < M)
                v = *(const uint4*)(A + (size_t)(bm + raA) * K + k0 + caA);
            *(uint4*)(sA + raA * SMA + caA) = v;
            uint4 w = *(const uint4*)(B + (size_t)(k0 + raB) * N + bn + caB);
            *(uint4*)(sB + raB * SMB + caB) = w;
        }
        __syncthreads();
        wmma::fragment<wmma::matrix_b, 16, 16, 16, __half, wmma::row_major> fb[2];
#pragma unroll
        for (int j = 0; j < 2; j++)
            wmma::load_matrix_sync(fb[j], sB + wn * 32 + j * 16, SMB);
#pragma unroll
        for (int i = 0; i < 4; i++) {
            wmma::fragment<wmma::matrix_a, 16, 16, 16, __half, wmma::row_major> fa;
            wmma::load_matrix_sync(fa, sA + (wm * 64 + i * 16) * SMA, SMA);
#pragma unroll
            for (int j = 0; j < 2; j++)
                wmma::mma_sync(fc[i][j], fa, fb[j], fc[i][j]);
        }
    }
    __syncthreads();  // all mma reads of sA/sB done before sC overwrite

#pragma unroll
    for (int i = 0; i < 4; i++)
#pragma unroll
        for (int j = 0; j < 2; j++)
            wmma::store_matrix_sync(sC + (size_t)(wm * 64 + i * 16) * SMC + wn * 32 + j * 16,
                                    fc[i][j], SMC, wmma::mem_row_major);
    __syncthreads();

    // fp16 C store: thread -> row tid>>1, 64-col half (tid&1)
    int row = tid >> 1, cbase = (tid & 1) * 64;
    if (bm + row < M) {
        __half* cp = C + (size_t)(bm + row) * N + bn + cbase;
        const float* crow = sC + row * SMC + cbase;
#pragma unroll
        for (int c = 0; c < 64; c += 8) {
            __half2 p0 = __floats2half2_rn(crow[c + 0], crow[c + 1]);
            __half2 p1 = __floats2half2_rn(crow[c + 2], crow[c + 3]);
            __half2 p2 = __floats2half2_rn(crow[c + 4], crow[c + 5]);
            __half2 p3 = __floats2half2_rn(crow[c + 6], crow[c + 7]);
            *(uint4*)(cp + c) = make_uint4(*(unsigned*)&p0, *(unsigned*)&p1,
                                           *(unsigned*)&p2, *(unsigned*)&p3);
        }
    }

    // fused scores: 2 threads per row, 64 cols each, combine via lane^1 shfl
    {
        float ps = 0.f, pd = 0.f;
        const float* arow = a_src + head * 128 + cbase;
        const float* drow = a_dst + head * 128 + cbase;
        const float* crow = sC + row * SMC + cbase;
#pragma unroll 16
        for (int c = 0; c < 64; c++) {
            float cv = crow[c];
            ps += cv * arow[c];
            pd += cv * drow[c];
        }
        ps += __shfl_xor_sync(0xffffffffu, ps, 1);
        pd += __shfl_xor_sync(0xffffffffu, pd, 1);
        if ((tid & 1) == 0 && bm + row < M) {
            ssrc[(bm + row) * H + head] = ps;
            sdst[(bm + row) * H + head] = pd;
        }
    }
}

// ---------------- layer0 fused softmax+aggregate+bias+ELU (fp16 out) -----------
__global__ __launch_bounds__(128) void msg0f(const int* __restrict__ off,
                                             const int* __restrict__ csrc,
                                             const float* __restrict__ ssrc,
                                             const float* __restrict__ sdst,
                                             const __half* __restrict__ h,
                                             const float* __restrict__ b0,
                                             __half* __restrict__ out,
                                             int nodeBase, int nodeEnd) {
    int node = nodeBase + blockIdx.x * 4 + (threadIdx.x >> 5);
    if (node >= nodeEnd) return;
    int lane = threadIdx.x & 31;
    int head = lane >> 4;
    int begin = off[node], end = off[node + 1];
    float sd = sdst[node * 2 + head];
    const __half* hb = h + lane * 8;
    float2 acc[4][4];
#pragma unroll
    for (int q = 0; q < 4; q++)
#pragma unroll
        for (int k = 0; k < 4; k++) acc[q][k] = make_float2(0.f, 0.f);
    float wsum = 0.f;
    int j = begin;
    for (; j + 4 <= end; j += 4) {
        int s0 = csrc[j], s1 = csrc[j + 1], s2 = csrc[j + 2], s3 = csrc[j + 3];
        float a0 = __expf(lrelu(ssrc[s0 * 2 + head] + sd));
        float a1 = __expf(lrelu(ssrc[s1 * 2 + head] + sd));
        float a2 = __expf(lrelu(ssrc[s2 * 2 + head] + sd));
        float a3 = __expf(lrelu(ssrc[s3 * 2 + head] + sd));
        wsum += (a0 + a1) + (a2 + a3);
        uint4 u0 = *(const uint4*)(hb + (size_t)s0 * 256);
        uint4 u1 = *(const uint4*)(hb + (size_t)s1 * 256);
        uint4 u2 = *(const uint4*)(hb + (size_t)s2 * 256);
        uint4 u3 = *(const uint4*)(hb + (size_t)s3 * 256);
#define ACC0(q, u, a)                                                     \
        {                                                                 \
            float2 f0 = __half22float2(*(const __half2*)&u.x);            \
            float2 f1 = __half22float2(*(const __half2*)&u.y);            \
            float2 f2 = __half22float2(*(const __half2*)&u.z);            \
            float2 f3 = __half22float2(*(const __half2*)&u.w);            \
            acc[q][0].x += a * f0.x; acc[q][0].y += a * f0.y;             \
            acc[q][1].x += a * f1.x; acc[q][1].y += a * f1.y;             \
            acc[q][2].x += a * f2.x; acc[q][2].y += a * f2.y;             \
            acc[q][3].x += a * f3.x; acc[q][3].y += a * f3.y;             \
        }
        ACC0(0, u0, a0) ACC0(1, u1, a1) ACC0(2, u2, a2) ACC0(3, u3, a3)
    }
    for (; j < end; j++) {
        int s0 = csrc[j];
        float a0 = __expf(lrelu(ssrc[s0 * 2 + head] + sd));
        wsum += a0;
        uint4 u0 = *(const uint4*)(hb + (size_t)s0 * 256);
        ACC0(0, u0, a0)
    }
#undef ACC0
    float r = 1.f / wsum;
    float4 bbA = *(const float4*)(b0 + lane * 8);
    float4 bbB = *(const float4*)(b0 + lane * 8 + 4);
    float v[8];
    v[0] = (acc[0][0].x + acc[1][0].x + acc[2][0].x + acc[3][0].x) * r + bbA.x;
    v[1] = (acc[0][0].y + acc[1][0].y + acc[2][0].y + acc[3][0].y) * r + bbA.y;
    v[2] = (acc[0][1].x + acc[1][1].x + acc[2][1].x + acc[3][1].x) * r + bbA.z;
    v[3] = (acc[0][1].y + acc[1][1].y + acc[2][1].y + acc[3][1].y) * r + bbA.w;
    v[4] = (acc[0][2].x + acc[1][2].x + acc[2][2].x + acc[3][2].x) * r + bbB.x;
    v[5] = (acc[0][2].y + acc[1][2].y + acc[2][2].y + acc[3][2].y) * r + bbB.y;
    v[6] = (acc[0][3].x + acc[1][3].x + acc[2][3].x + acc[3][3].x) * r + bbB.z;
    v[7] = (acc[0][3].y + acc[1][3].y + acc[2][3].y + acc[3][3].y) * r + bbB.w;
#pragma unroll
    for (int k = 0; k < 8; k++) v[k] = v[k] > 0.f ? v[k] : (expf(v[k]) - 1.f);
    __half2 p0 = __floats2half2_rn(v[0], v[1]);
    __half2 p1 = __floats2half2_rn(v[2], v[3]);
    __half2 p2 = __floats2half2_rn(v[4], v[5]);
    __half2 p3 = __floats2half2_rn(v[6], v[7]);
    *(uint4*)(out + (size_t)node * 256 + lane * 8) =
        make_uint4(*(unsigned*)&p0, *(unsigned*)&p1, *(unsigned*)&p2, *(unsigned*)&p3);
}

// ---------------- layer1 fused softmax+aggregate+residual+bias -----------------
__global__ __launch_bounds__(128) void msg1f(const int* __restrict__ off,
                                             const int* __restrict__ csrc,
                                             const float* __restrict__ ssrc,
                                             const float* __restrict__ sdst,
                                             const __half* __restrict__ h,
                                             const float* __restrict__ x,
                                             const float* __restrict__ b1,
                                             float* __restrict__ out) {
    int node = blockIdx.x * 4 + (threadIdx.x >> 5);
    if (node >= NN) return;
    int lane = threadIdx.x & 31;
    int begin = off[node], end = off[node + 1];
    float sd = sdst[node];
    const __half* hb = h + lane * 4;
    float2 acc[4][2];
#pragma unroll
    for (int q = 0; q < 4; q++) {
        acc[q][0] = make_float2(0.f, 0.f);
        acc[q][1] = make_float2(0.f, 0.f);
    }
    float wsum = 0.f;
    int j = begin;
    for (; j + 4 <= end; j += 4) {
        int s0 = csrc[j], s1 = csrc[j + 1], s2 = csrc[j + 2], s3 = csrc[j + 3];
        float a0 = __expf(lrelu(ssrc[s0] + sd));
        float a1 = __expf(lrelu(ssrc[s1] + sd));
        float a2 = __expf(lrelu(ssrc[s2] + sd));
        float a3 = __expf(lrelu(ssrc[s3] + sd));
        wsum += (a0 + a1) + (a2 + a3);
        uint2 u0 = *(const uint2*)(hb + (size_t)s0 * 128);
        uint2 u1 = *(const uint2*)(hb + (size_t)s1 * 128);
        uint2 u2 = *(const uint2*)(hb + (size_t)s2 * 128);
        uint2 u3 = *(const uint2*)(hb + (size_t)s3 * 128);
#define ACC1(q, u, a)                                                     \
        {                                                                 \
            float2 f0 = __half22float2(*(const __half2*)&u.x);            \
            float2 f1 = __half22float2(*(const __half2*)&u.y);            \
            acc[q][0].x += a * f0.x; acc[q][0].y += a * f0.y;             \
            acc[q][1].x += a * f1.x; acc[q][1].y += a * f1.y;             \
        }
        ACC1(0, u0, a0) ACC1(1, u1, a1) ACC1(2, u2, a2) ACC1(3, u3, a3)
    }
    for (; j < end; j++) {
        int s0 = csrc[j];
        float a0 = __expf(lrelu(ssrc[s0] + sd));
        wsum += a0;
        uint2 u0 = *(const uint2*)(hb + (size_t)s0 * 128);
        ACC1(0, u0, a0)
    }
#undef ACC1
    float r = 1.f / wsum;
    float4 xb = *(const float4*)(x + (size_t)node * 128 + lane * 4);
    float4 bb = *(const float4*)(b1 + lane * 4);
    float4 o;
    o.x = (acc[0][0].x + acc[1][0].x + acc[2][0].x + acc[3][0].x) * r + xb.x + bb.x;
    o.y = (acc[0][0].y + acc[1][0].y + acc[2][0].y + acc[3][0].y) * r + xb.y + bb.y;
    o.z = (acc[0][1].x + acc[1][1].x + acc[2][1].x + acc[3][1].x) * r + xb.z + bb.z;
    o.w = (acc[0][1].y + acc[1][1].y + acc[2][1].y + acc[3][1].y) * r + xb.w + bb.w;
    *(float4*)(out + (size_t)node * 128 + lane * 4) = o;
}

// ---------------- launch -------------------------------------------------------
extern "C" void kernel_launch(void* const* d_in, const int* in_sizes, int n_in,
                              void* d_out, int out_size) {
    const float* x      = (const float*)d_in[0];
    const float* W0     = (const float*)d_in[1];
    const float* a_src0 = (const float*)d_in[2];
    const float* a_dst0 = (const float*)d_in[3];
    const float* b0     = (const float*)d_in[4];
    const float* W1     = (const float*)d_in[5];
    const float* a_src1 = (const float*)d_in[6];
    const float* a_dst1 = (const float*)d_in[7];
    const float* b1     = (const float*)d_in[8];
    const int*   ei     = (const int*)d_in[9];
    int E0 = in_sizes[9] / 2;
    int Etot = E0 + NN;
    const int* src = ei;
    const int* dst = ei + E0;
    float* out = (float*)d_out;

    __half *xh, *W0h, *W1h, *h0, *out0h, *h1;
    float *ssrc0, *sdst0, *ssrc1, *sdst1;
    int *cnt, *off, *cursor, *csrc;
    cudaGetSymbolAddress((void**)&xh, g_xh);
    cudaGetSymbolAddress((void**)&W0h, g_W0h);
    cudaGetSymbolAddress((void**)&W1h, g_W1h);
    cudaGetSymbolAddress((void**)&h0, g_h0);
    cudaGetSymbolAddress((void**)&out0h, g_out0h);
    cudaGetSymbolAddress((void**)&h1, g_h1);
    cudaGetSymbolAddress((void**)&ssrc0, g_ssrc0);
    cudaGetSymbolAddress((void**)&sdst0, g_sdst0);
    cudaGetSymbolAddress((void**)&ssrc1, g_ssrc1);
    cudaGetSymbolAddress((void**)&sdst1, g_sdst1);
    cudaGetSymbolAddress((void**)&cnt, g_cnt);
    cudaGetSymbolAddress((void**)&off, g_off);
    cudaGetSymbolAddress((void**)&cursor, g_cursor);
    cudaGetSymbolAddress((void**)&csrc, g_csrc);

    cudaFuncSetAttribute(gemmW, cudaFuncAttributeMaxDynamicSharedMemorySize, GEMM_SMEM);

    cudaStream_t sB;
    cudaStreamCreateWithFlags(&sB, cudaStreamNonBlocking);
    cudaEvent_t evFork, evB, evM0a, evG1a;
    cudaEventCreateWithFlags(&evFork, cudaEventDisableTiming);
    cudaEventCreateWithFlags(&evB, cudaEventDisableTiming);
    cudaEventCreateWithFlags(&evM0a, cudaEventDisableTiming);
    cudaEventCreateWithFlags(&evG1a, cudaEventDisableTiming);

    cudaEventRecord(evFork, 0);
    cudaStreamWaitEvent(sB, evFork, 0);

    // ---- CSR build on side stream ----
    filli<<<(NN + 255) / 256, 256, 0, sB>>>(cnt, NN, 1);
    histK<<<(E0 + 255) / 256, 256, 0, sB>>>(dst, E0, cnt);
    scanK<<<1, 1024, 0, sB>>>(cnt, off, cursor);
    scatterK<<<(Etot + 255) / 256, 256, 0, sB>>>(src, dst, E0, Etot, cursor, csrc);
    cudaEventRecord(evB, sB);

    // ---- fp16 conversions + layer0 GEMM on main ----
    f2h<<<(NN * 128 / 4 + 255) / 256, 256>>>(x, xh, NN * 128 / 4);
    f2h<<<(128 * 256 / 4 + 255) / 256, 256>>>(W0, W0h, 128 * 256 / 4);
    f2h<<<(256 * 128 / 4 + 255) / 256, 256>>>(W1, W1h, 256 * 128 / 4);
    gemmW<<<dim3(2, (NN + 127) / 128), 256, GEMM_SMEM>>>(
        xh, W0h, h0, a_src0, a_dst0, ssrc0, sdst0, NN, 256, 128, 2, 0);
    cudaStreamWaitEvent(0, evB, 0);

    // ---- msg0f chunk A (nodes [0, SPLIT)) ----
    msg0f<<<SPLIT / 4, 128>>>(off, csrc, ssrc0, sdst0, h0, b0, out0h, 0, SPLIT);
    cudaEventRecord(evM0a, 0);

    // ---- gemm1 chunk A on side stream (rows [0, SPLIT)) — overlaps msg0f B ----
    cudaStreamWaitEvent(sB, evM0a, 0);
    gemmW<<<dim3(1, SPLIT / 128), 256, GEMM_SMEM, sB>>>(
        out0h, W1h, h1, a_src1, a_dst1, ssrc1, sdst1, NN, 128, 256, 1, 0);
    cudaEventRecord(evG1a, sB);

    // ---- msg0f chunk B (nodes [SPLIT, NN)) on main ----
    msg0f<<<(NN - SPLIT + 3) / 4, 128>>>(off, csrc, ssrc0, sdst0, h0, b0, out0h,
                                         SPLIT, NN);

    // ---- gemm1 chunk B on main (rows [SPLIT, NN)) ----
    gemmW<<<dim3(1, (NN - SPLIT + 127) / 128), 256, GEMM_SMEM>>>(
        out0h, W1h, h1, a_src1, a_dst1, ssrc1, sdst1, NN, 128, 256, 1, SPLIT);
    cudaStreamWaitEvent(0, evG1a, 0);

    // ---- msg1f (full) ----
    msg1f<<<(NN + 3) / 4, 128>>>(off, csrc, ssrc1, sdst1, h1, x, b1, out);

    cudaEventDestroy(evFork);
    cudaEventDestroy(evB);
    cudaEventDestroy(evM0a);
    cudaEventDestroy(evG1a);
    cudaStreamDestroy(sB);
}